// round 7
// baseline (speedup 1.0000x reference)
#include <cuda_runtime.h>

#define T_SEQ 2048
#define B_SZ  512

// h1 scratch for the deferred dense head (134 MB)
__device__ __align__(16) float g_h1[(size_t)T_SEQ * B_SZ * 32];

typedef unsigned long long u64;

// ---------- packed f32x2 helpers ----------
__device__ __forceinline__ u64 pack2(float a, float b) {
    u64 d; asm("mov.b64 %0,{%1,%2};" : "=l"(d) : "f"(a), "f"(b)); return d;
}
__device__ __forceinline__ void unpack2(u64 v, float& a, float& b) {
    asm("mov.b64 {%0,%1},%2;" : "=f"(a), "=f"(b) : "l"(v));
}
__device__ __forceinline__ u64 fma2(u64 a, u64 b, u64 c) {
    u64 d; asm("fma.rn.f32x2 %0,%1,%2,%3;" : "=l"(d) : "l"(a), "l"(b), "l"(c)); return d;
}

// ---------- activations via HW MUFU tanh (validated R6, err ~5e-6) ----------
__device__ __forceinline__ float htanh(float x) {
    float y; asm("tanh.approx.f32 %0,%1;" : "=f"(y) : "f"(x)); return y;
}
__device__ __forceinline__ float sigm(float x)  { return fmaf(htanh(0.5f * x), 0.5f, 0.5f); }
__device__ __forceinline__ float tanhf_(float x){ return htanh(x); }

// =====================================================================
// Fused 2-layer LSTM. One trio (3 warps) per block; EACH WARP CARRIES
// TWO batch elements with the same 128 weight registers:
//   role 0: layer-0 cell              (h0[t] at tick n = t)
//   role 1: layer-1 input projection  (xp1[t] at tick n = t+1)
//   role 2: layer-1 cell              (h1[t] at tick n = t+2)
// 4 independent fma2 chains per warp (elem A/B x if/go) -> latency is
// issue-dominated; weights amortized 2x; barriers amortized 2x.
// 256 blocks x 96 threads, 2 blocks/SM.
// =====================================================================
__global__ void __launch_bounds__(96, 2)
k_fused(const float* __restrict__ x,
        const float* __restrict__ Wih0, const float* __restrict__ Whh0,
        const float* __restrict__ bih0, const float* __restrict__ bhh0,
        const float* __restrict__ Wih1, const float* __restrict__ Whh1,
        const float* __restrict__ bih1, const float* __restrict__ bhh1)
{
    __shared__ __align__(16) float h0ring[2][2][64];   // [elem][slot] duplicated {h,h}
    __shared__ __align__(16) u64   pring[2][2][64];    // [elem][slot] {i,f}/{g,o}
    __shared__ __align__(16) float h1ring[2][2][64];

    const int tid  = threadIdx.x;
    const int role = tid >> 5, j = tid & 31;
    const int b0   = blockIdx.x * 2, b1 = b0 + 1;

    for (int i = tid; i < 2 * 2 * 64; i += 96) {
        ((float*)h0ring)[i] = 0.f;
        ((float*)h1ring)[i] = 0.f;
    }

    // per-role weight matrix -> 64 u64 regs of gate-pair columns (shared by both elems)
    const float* Wsrc = (role == 0) ? Whh0 : (role == 1) ? Wih1 : Whh1;
    u64 w_if[32], w_go[32];
#pragma unroll
    for (int k = 0; k < 32; k++) {
        w_if[k] = pack2(Wsrc[j * 32 + k],        Wsrc[(32 + j) * 32 + k]);
        w_go[k] = pack2(Wsrc[(64 + j) * 32 + k], Wsrc[(96 + j) * 32 + k]);
    }

    u64 wx_if = 0, wx_go = 0, bs_if = 0, bs_go = 0;
    if (role == 0) {
        wx_if = pack2(Wih0[j],      Wih0[32 + j]);
        wx_go = pack2(Wih0[64 + j], Wih0[96 + j]);
        bs_if = pack2(bih0[j] + bhh0[j],           bih0[32 + j] + bhh0[32 + j]);
        bs_go = pack2(bih0[64 + j] + bhh0[64 + j], bih0[96 + j] + bhh0[96 + j]);
    } else if (role == 1) {
        bs_if = pack2(bih1[j] + bhh1[j],           bih1[32 + j] + bhh1[32 + j]);
        bs_go = pack2(bih1[64 + j] + bhh1[64 + j], bih1[96 + j] + bhh1[96 + j]);
    }

    float cA = 0.f, cB = 0.f;                     // cell states (roles 0 and 2)
    float xtA = x[b0], xtB = x[b1];               // x[t=0]  (IN == 1)

    __syncthreads();

#pragma unroll 1
    for (int n = 0; n < T_SEQ + 2; n++) {
        if (role == 0) {
            if (n < T_SEQ) {
                float xnA = (n + 1 < T_SEQ) ? x[(n + 1) * B_SZ + b0] : 0.f;
                float xnB = (n + 1 < T_SEQ) ? x[(n + 1) * B_SZ + b1] : 0.f;
                u64 aifA = fma2(pack2(xtA, xtA), wx_if, bs_if);
                u64 agoA = fma2(pack2(xtA, xtA), wx_go, bs_go);
                u64 aifB = fma2(pack2(xtB, xtB), wx_if, bs_if);
                u64 agoB = fma2(pack2(xtB, xtB), wx_go, bs_go);
                const ulonglong2* hvA =
                    reinterpret_cast<const ulonglong2*>(h0ring[0][(n + 1) & 1]); // (n-1)&1
                const ulonglong2* hvB =
                    reinterpret_cast<const ulonglong2*>(h0ring[1][(n + 1) & 1]);
#pragma unroll
                for (int m = 0; m < 16; m++) {
                    ulonglong2 hA = hvA[m], hB = hvB[m];
                    aifA = fma2(hA.x, w_if[2*m],   aifA);
                    agoA = fma2(hA.x, w_go[2*m],   agoA);
                    aifB = fma2(hB.x, w_if[2*m],   aifB);
                    agoB = fma2(hB.x, w_go[2*m],   agoB);
                    aifA = fma2(hA.y, w_if[2*m+1], aifA);
                    agoA = fma2(hA.y, w_go[2*m+1], agoA);
                    aifB = fma2(hB.y, w_if[2*m+1], aifB);
                    agoB = fma2(hB.y, w_go[2*m+1], agoB);
                }
                float gi, gf, gg, go;
                unpack2(aifA, gi, gf); unpack2(agoA, gg, go);
                gi = sigm(gi); gf = sigm(gf); gg = tanhf_(gg); go = sigm(go);
                cA = gf * cA + gi * gg;
                float hA = go * tanhf_(cA);
                unpack2(aifB, gi, gf); unpack2(agoB, gg, go);
                gi = sigm(gi); gf = sigm(gf); gg = tanhf_(gg); go = sigm(go);
                cB = gf * cB + gi * gg;
                float hB = go * tanhf_(cB);
                reinterpret_cast<u64*>(h0ring[0][n & 1])[j] = pack2(hA, hA);
                reinterpret_cast<u64*>(h0ring[1][n & 1])[j] = pack2(hB, hB);
                xtA = xnA; xtB = xnB;
            }
        } else if (role == 1) {
            if (n >= 1 && n <= T_SEQ) {
                const ulonglong2* hvA =
                    reinterpret_cast<const ulonglong2*>(h0ring[0][(n - 1) & 1]);
                const ulonglong2* hvB =
                    reinterpret_cast<const ulonglong2*>(h0ring[1][(n - 1) & 1]);
                u64 aifA = bs_if, agoA = bs_go, aifB = bs_if, agoB = bs_go;
#pragma unroll
                for (int m = 0; m < 16; m++) {
                    ulonglong2 hA = hvA[m], hB = hvB[m];
                    aifA = fma2(hA.x, w_if[2*m],   aifA);
                    agoA = fma2(hA.x, w_go[2*m],   agoA);
                    aifB = fma2(hB.x, w_if[2*m],   aifB);
                    agoB = fma2(hB.x, w_go[2*m],   agoB);
                    aifA = fma2(hA.y, w_if[2*m+1], aifA);
                    agoA = fma2(hA.y, w_go[2*m+1], agoA);
                    aifB = fma2(hB.y, w_if[2*m+1], aifB);
                    agoB = fma2(hB.y, w_go[2*m+1], agoB);
                }
                pring[0][(n - 1) & 1][j]      = aifA;
                pring[0][(n - 1) & 1][32 + j] = agoA;
                pring[1][(n - 1) & 1][j]      = aifB;
                pring[1][(n - 1) & 1][32 + j] = agoB;
            }
        } else {
            if (n >= 2) {
                const int t = n - 2;
                u64 aifA = pring[0][n & 1][j];        // slot (n-2)&1 == n&1
                u64 agoA = pring[0][n & 1][32 + j];
                u64 aifB = pring[1][n & 1][j];
                u64 agoB = pring[1][n & 1][32 + j];
                const ulonglong2* hvA =
                    reinterpret_cast<const ulonglong2*>(h1ring[0][(n + 1) & 1]); // (n-1)&1
                const ulonglong2* hvB =
                    reinterpret_cast<const ulonglong2*>(h1ring[1][(n + 1) & 1]);
#pragma unroll
                for (int m = 0; m < 16; m++) {
                    ulonglong2 hA = hvA[m], hB = hvB[m];
                    aifA = fma2(hA.x, w_if[2*m],   aifA);
                    agoA = fma2(hA.x, w_go[2*m],   agoA);
                    aifB = fma2(hB.x, w_if[2*m],   aifB);
                    agoB = fma2(hB.x, w_go[2*m],   agoB);
                    aifA = fma2(hA.y, w_if[2*m+1], aifA);
                    agoA = fma2(hA.y, w_go[2*m+1], agoA);
                    aifB = fma2(hB.y, w_if[2*m+1], aifB);
                    agoB = fma2(hB.y, w_go[2*m+1], agoB);
                }
                float gi, gf, gg, go;
                unpack2(aifA, gi, gf); unpack2(agoA, gg, go);
                gi = sigm(gi); gf = sigm(gf); gg = tanhf_(gg); go = sigm(go);
                cA = gf * cA + gi * gg;
                float hA = go * tanhf_(cA);
                unpack2(aifB, gi, gf); unpack2(agoB, gg, go);
                gi = sigm(gi); gf = sigm(gf); gg = tanhf_(gg); go = sigm(go);
                cB = gf * cB + gi * gg;
                float hB = go * tanhf_(cB);
                reinterpret_cast<u64*>(h1ring[0][n & 1])[j] = pack2(hA, hA);
                reinterpret_cast<u64*>(h1ring[1][n & 1])[j] = pack2(hB, hB);
                g_h1[(size_t)t * (B_SZ * 32) + b0 * 32 + j] = hA;   // coalesced
                g_h1[(size_t)t * (B_SZ * 32) + b1 * 32 + j] = hB;
            }
        }
        __syncthreads();               // 3-warp barrier, this trio only
    }
}

// =====================================================================
// Dense head: out[t,b] = sum_j h1[t,b,j]*Wd[j] + bd. Memory-bound (~30us).
// =====================================================================
__global__ void __launch_bounds__(256)
k_head(const float* __restrict__ Wd, const float* __restrict__ bd,
       float* __restrict__ out)
{
    const int gw = blockIdx.x * 8 + (threadIdx.x >> 5);
    const int j  = threadIdx.x & 31;
    const size_t r = (size_t)gw * 4 + (j >> 3);
    const int q  = j & 7;

    float4 h = reinterpret_cast<const float4*>(g_h1)[r * 8 + q];
    float4 w = reinterpret_cast<const float4*>(Wd)[q];
    float s = h.x * w.x + h.y * w.y + h.z * w.z + h.w * w.w;
    s += __shfl_xor_sync(0xffffffffu, s, 1);
    s += __shfl_xor_sync(0xffffffffu, s, 2);
    s += __shfl_xor_sync(0xffffffffu, s, 4);
    if (q == 0) out[r] = s + bd[0];
}

// =====================================================================
extern "C" void kernel_launch(void* const* d_in, const int* in_sizes, int n_in,
                              void* d_out, int out_size)
{
    const float* x    = (const float*)d_in[0];
    const float* Wih0 = (const float*)d_in[1];
    const float* Whh0 = (const float*)d_in[2];
    const float* bih0 = (const float*)d_in[3];
    const float* bhh0 = (const float*)d_in[4];
    const float* Wih1 = (const float*)d_in[5];
    const float* Whh1 = (const float*)d_in[6];
    const float* bih1 = (const float*)d_in[7];
    const float* bhh1 = (const float*)d_in[8];
    const float* Wd   = (const float*)d_in[9];
    const float* bd   = (const float*)d_in[10];

    k_fused<<<256, 96>>>(x, Wih0, Whh0, bih0, bhh0, Wih1, Whh1, bih1, bhh1);
    k_head<<<32768, 256>>>(Wd, bd, (float*)d_out);
}

// round 8
// speedup vs baseline: 1.5438x; 1.5438x over previous
#include <cuda_runtime.h>

#define T_SEQ 2048
#define B_SZ  512

// h1 scratch for the deferred dense head (134 MB)
__device__ __align__(16) float g_h1[(size_t)T_SEQ * B_SZ * 32];

typedef unsigned long long u64;

// ---------- packed f32x2 helpers ----------
__device__ __forceinline__ u64 pack2(float a, float b) {
    u64 d; asm("mov.b64 %0,{%1,%2};" : "=l"(d) : "f"(a), "f"(b)); return d;
}
__device__ __forceinline__ void unpack2(u64 v, float& a, float& b) {
    asm("mov.b64 {%0,%1},%2;" : "=f"(a), "=f"(b) : "l"(v));
}
__device__ __forceinline__ u64 fma2(u64 a, u64 b, u64 c) {
    u64 d; asm("fma.rn.f32x2 %0,%1,%2,%3;" : "=l"(d) : "l"(a), "l"(b), "l"(c)); return d;
}

// ---------- activations via HW MUFU tanh (validated R6, err ~5e-6) ----------
__device__ __forceinline__ float htanh(float x) {
    float y; asm("tanh.approx.f32 %0,%1;" : "=f"(y) : "f"(x)); return y;
}
__device__ __forceinline__ float sigm(float x)  { return fmaf(htanh(0.5f * x), 0.5f, 0.5f); }
__device__ __forceinline__ float tanhf_(float x){ return htanh(x); }

// =====================================================================
// Fused 2-layer LSTM. Block = 4 trios = 12 warps (384 threads).
//   trio e = wid/3, role = wid%3:
//     role 0: layer-0 cell              (h0[t] at tick n = t)
//     role 1: layer-1 input projection  (xp1[t] at tick n = t+1)
//     role 2: layer-1 cell              (h1[t] at tick n = t+2)
// This mapping spreads each trio's 3 warps over 3 DIFFERENT SMSPs and
// gives every SMSP exactly 3 warps: one L0-cell + one proj + one L1-cell
// from different trios -> full 4-SMSP coverage (96-thr blocks left SMSP3
// idle), per-SMSP fma2 pipe occupancy drops 512 -> 384 cyc/tick.
// Plain block-wide __syncthreads per tick (floor 7 cyc; measured trio
// coupling cost ~2% — cheaper than named barriers' ~47 cyc).
// Inner loop identical to R6 (validated codegen).
// =====================================================================
__global__ void __launch_bounds__(384, 1)
k_fused(const float* __restrict__ x,
        const float* __restrict__ Wih0, const float* __restrict__ Whh0,
        const float* __restrict__ bih0, const float* __restrict__ bhh0,
        const float* __restrict__ Wih1, const float* __restrict__ Whh1,
        const float* __restrict__ bih1, const float* __restrict__ bhh1)
{
    __shared__ __align__(16) float h0ring[4][2][64];   // [trio][slot] duplicated {h,h}
    __shared__ __align__(16) u64   pring[4][2][64];    // [trio][slot] {i,f}/{g,o}
    __shared__ __align__(16) float h1ring[4][2][64];

    const int tid  = threadIdx.x;
    const int wid  = tid >> 5, j = tid & 31;
    const int e    = wid / 3;              // trio (0..3)
    const int role = wid - 3 * e;          // 0=L0 cell, 1=proj, 2=L1 cell
    const int b    = blockIdx.x * 4 + e;

    // zero initial hidden states (both ring slots)
    for (int i = tid; i < 4 * 2 * 64; i += 384) {
        ((float*)h0ring)[i] = 0.f;
        ((float*)h1ring)[i] = 0.f;
    }

    // per-role weight matrix -> 64 u64 regs of gate-pair columns
    const float* Wsrc = (role == 0) ? Whh0 : (role == 1) ? Wih1 : Whh1;
    u64 w_if[32], w_go[32];
#pragma unroll
    for (int k = 0; k < 32; k++) {
        w_if[k] = pack2(Wsrc[j * 32 + k],        Wsrc[(32 + j) * 32 + k]);
        w_go[k] = pack2(Wsrc[(64 + j) * 32 + k], Wsrc[(96 + j) * 32 + k]);
    }

    u64 wx_if = 0, wx_go = 0, bs_if = 0, bs_go = 0;
    if (role == 0) {
        wx_if = pack2(Wih0[j],      Wih0[32 + j]);
        wx_go = pack2(Wih0[64 + j], Wih0[96 + j]);
        bs_if = pack2(bih0[j] + bhh0[j],           bih0[32 + j] + bhh0[32 + j]);
        bs_go = pack2(bih0[64 + j] + bhh0[64 + j], bih0[96 + j] + bhh0[96 + j]);
    } else if (role == 1) {
        bs_if = pack2(bih1[j] + bhh1[j],           bih1[32 + j] + bhh1[32 + j]);
        bs_go = pack2(bih1[64 + j] + bhh1[64 + j], bih1[96 + j] + bhh1[96 + j]);
    }

    float c  = 0.f;                    // cell state (roles 0 and 2)
    float xt = x[b];                   // x[t=0]  (IN == 1)

    __syncthreads();                   // init visible

#pragma unroll 1
    for (int n = 0; n < T_SEQ + 2; n++) {
        if (role == 0) {
            if (n < T_SEQ) {
                float xn = (n + 1 < T_SEQ) ? x[(n + 1) * B_SZ + b] : 0.f;
                u64 xs  = pack2(xt, xt);
                u64 aif = fma2(xs, wx_if, bs_if);
                u64 ago = fma2(xs, wx_go, bs_go);
                const ulonglong2* hv =
                    reinterpret_cast<const ulonglong2*>(h0ring[e][(n + 1) & 1]); // (n-1)&1
#pragma unroll
                for (int m = 0; m < 16; m++) {
                    ulonglong2 h2 = hv[m];              // {h2m,h2m},{h2m+1,h2m+1}
                    aif = fma2(h2.x, w_if[2*m],   aif);
                    ago = fma2(h2.x, w_go[2*m],   ago);
                    aif = fma2(h2.y, w_if[2*m+1], aif);
                    ago = fma2(h2.y, w_go[2*m+1], ago);
                }
                float gi, gf, gg, go;
                unpack2(aif, gi, gf); unpack2(ago, gg, go);
                gi = sigm(gi); gf = sigm(gf); gg = tanhf_(gg); go = sigm(go);
                c = gf * c + gi * gg;
                float h = go * tanhf_(c);
                reinterpret_cast<u64*>(h0ring[e][n & 1])[j] = pack2(h, h);
                xt = xn;
            }
        } else if (role == 1) {
            if (n >= 1 && n <= T_SEQ) {
                const ulonglong2* hv =
                    reinterpret_cast<const ulonglong2*>(h0ring[e][(n - 1) & 1]);
                u64 aif = bs_if, ago = bs_go;
#pragma unroll
                for (int m = 0; m < 16; m++) {
                    ulonglong2 h2 = hv[m];
                    aif = fma2(h2.x, w_if[2*m],   aif);
                    ago = fma2(h2.x, w_go[2*m],   ago);
                    aif = fma2(h2.y, w_if[2*m+1], aif);
                    ago = fma2(h2.y, w_go[2*m+1], ago);
                }
                pring[e][(n - 1) & 1][j]      = aif;
                pring[e][(n - 1) & 1][32 + j] = ago;
            }
        } else {
            if (n >= 2) {
                const int t = n - 2;
                const u64* pv = pring[e][n & 1];       // slot (n-2)&1 == n&1
                u64 aif = pv[j];
                u64 ago = pv[32 + j];
                const ulonglong2* hv =
                    reinterpret_cast<const ulonglong2*>(h1ring[e][(n + 1) & 1]); // (n-1)&1
#pragma unroll
                for (int m = 0; m < 16; m++) {
                    ulonglong2 h2 = hv[m];
                    aif = fma2(h2.x, w_if[2*m],   aif);
                    ago = fma2(h2.x, w_go[2*m],   ago);
                    aif = fma2(h2.y, w_if[2*m+1], aif);
                    ago = fma2(h2.y, w_go[2*m+1], ago);
                }
                float gi, gf, gg, go;
                unpack2(aif, gi, gf); unpack2(ago, gg, go);
                gi = sigm(gi); gf = sigm(gf); gg = tanhf_(gg); go = sigm(go);
                c = gf * c + gi * gg;
                float h = go * tanhf_(c);
                reinterpret_cast<u64*>(h1ring[e][n & 1])[j] = pack2(h, h);
                g_h1[(size_t)t * (B_SZ * 32) + b * 32 + j] = h;   // coalesced
            }
        }
        __syncthreads();               // block-wide, floor 7 cyc
    }
}

// =====================================================================
// Dense head: out[t,b] = sum_j h1[t,b,j]*Wd[j] + bd. Memory-bound (~30us).
// =====================================================================
__global__ void __launch_bounds__(256)
k_head(const float* __restrict__ Wd, const float* __restrict__ bd,
       float* __restrict__ out)
{
    const int gw = blockIdx.x * 8 + (threadIdx.x >> 5);
    const int j  = threadIdx.x & 31;
    const size_t r = (size_t)gw * 4 + (j >> 3);
    const int q  = j & 7;

    float4 h = reinterpret_cast<const float4*>(g_h1)[r * 8 + q];
    float4 w = reinterpret_cast<const float4*>(Wd)[q];
    float s = h.x * w.x + h.y * w.y + h.z * w.z + h.w * w.w;
    s += __shfl_xor_sync(0xffffffffu, s, 1);
    s += __shfl_xor_sync(0xffffffffu, s, 2);
    s += __shfl_xor_sync(0xffffffffu, s, 4);
    if (q == 0) out[r] = s + bd[0];
}

// =====================================================================
extern "C" void kernel_launch(void* const* d_in, const int* in_sizes, int n_in,
                              void* d_out, int out_size)
{
    const float* x    = (const float*)d_in[0];
    const float* Wih0 = (const float*)d_in[1];
    const float* Whh0 = (const float*)d_in[2];
    const float* bih0 = (const float*)d_in[3];
    const float* bhh0 = (const float*)d_in[4];
    const float* Wih1 = (const float*)d_in[5];
    const float* Whh1 = (const float*)d_in[6];
    const float* bih1 = (const float*)d_in[7];
    const float* bhh1 = (const float*)d_in[8];
    const float* Wd   = (const float*)d_in[9];
    const float* bd   = (const float*)d_in[10];

    k_fused<<<128, 384>>>(x, Wih0, Whh0, bih0, bhh0, Wih1, Whh1, bih1, bhh1);
    k_head<<<32768, 256>>>(Wd, bd, (float*)d_out);
}

// round 11
// speedup vs baseline: 1.7014x; 1.1021x over previous
#include <cuda_runtime.h>

#define T_SEQ 2048
#define B_SZ  512
#define NTICK (T_SEQ / 2 + 2)   // 2 timesteps per tick + 2 pipeline fill

// h1 scratch for the deferred dense head (134 MB)
__device__ __align__(16) float g_h1[(size_t)T_SEQ * B_SZ * 32];

typedef unsigned long long u64;

// ---------- packed f32x2 helpers ----------
__device__ __forceinline__ u64 pack2(float a, float b) {
    u64 d; asm("mov.b64 %0,{%1,%2};" : "=l"(d) : "f"(a), "f"(b)); return d;
}
__device__ __forceinline__ void unpack2(u64 v, float& a, float& b) {
    asm("mov.b64 {%0,%1},%2;" : "=f"(a), "=f"(b) : "l"(v));
}
__device__ __forceinline__ u64 fma2(u64 a, u64 b, u64 c) {
    u64 d; asm("fma.rn.f32x2 %0,%1,%2,%3;" : "=l"(d) : "l"(a), "l"(b), "l"(c)); return d;
}
__device__ __forceinline__ u64 add2(u64 a, u64 b) {
    u64 d; asm("add.rn.f32x2 %0,%1,%2;" : "=l"(d) : "l"(a), "l"(b)); return d;
}

// ---------- activations via HW MUFU tanh (validated R6, err ~5e-6) ----------
__device__ __forceinline__ float htanh(float x) {
    float y; asm("tanh.approx.f32 %0,%1;" : "=f"(y) : "f"(x)); return y;
}
__device__ __forceinline__ float sigm(float x)  { return fmaf(htanh(0.5f * x), 0.5f, 0.5f); }
__device__ __forceinline__ float tanhf_(float x){ return htanh(x); }

// Gate-pair matvec: two half-chains (k 0..15 / 16..31) per accumulator,
// combined with one add2 -> 4 independent 16-deep chains, half the
// dependency latency of the 32-deep version. Same LDS pattern as R6.
__device__ __forceinline__ void matvec(const ulonglong2* __restrict__ hv,
                                       const u64* __restrict__ w_if,
                                       const u64* __restrict__ w_go,
                                       u64 if0, u64 go0, u64& aif, u64& ago)
{
    u64 aL = if0, gL = go0, aH = 0ull, gH = 0ull;
#pragma unroll
    for (int m = 0; m < 8; m++) {
        ulonglong2 h2 = hv[m];
        aL = fma2(h2.x, w_if[2*m],   aL);
        gL = fma2(h2.x, w_go[2*m],   gL);
        aL = fma2(h2.y, w_if[2*m+1], aL);
        gL = fma2(h2.y, w_go[2*m+1], gL);
    }
#pragma unroll
    for (int m = 8; m < 16; m++) {
        ulonglong2 h2 = hv[m];
        aH = fma2(h2.x, w_if[2*m],   aH);
        gH = fma2(h2.x, w_go[2*m],   gH);
        aH = fma2(h2.y, w_if[2*m+1], aH);
        gH = fma2(h2.y, w_go[2*m+1], gH);
    }
    aif = add2(aL, aH);
    ago = add2(gL, gH);
}

__device__ __forceinline__ float cellstep(u64 aif, u64 ago, float& c) {
    float gi, gf, gg, go;
    unpack2(aif, gi, gf); unpack2(ago, gg, go);
    gi = sigm(gi); gf = sigm(gf); gg = tanhf_(gg); go = sigm(go);
    c = gf * c + gi * gg;
    return go * tanhf_(c);
}

// =====================================================================
// Fused 2-layer LSTM. One trio (3 warps) per block (R6 skeleton),
// TWO TIMESTEPS PER BARRIER TICK:
//   role 0: layer-0 cell       (h0[2m], h0[2m+1] at tick m)
//   role 1: layer-1 input proj (xp1 pair of tick m-1; two independent matvecs)
//   role 2: layer-1 cell       (h1 pair of tick m-2)
// role = (wid + blockIdx) % 3 (R6's SMSP role mixing, validated).
// Rings: [tick-slot][step-in-tick]; intra-tick fresh-h reads use
// __syncwarp (23 cyc) instead of a block barrier.
// 512 blocks x 96 threads, 4 blocks/SM.
// =====================================================================
__global__ void __launch_bounds__(96, 4)
k_fused(const float* __restrict__ x,
        const float* __restrict__ Wih0, const float* __restrict__ Whh0,
        const float* __restrict__ bih0, const float* __restrict__ bhh0,
        const float* __restrict__ Wih1, const float* __restrict__ Whh1,
        const float* __restrict__ bih1, const float* __restrict__ bhh1)
{
    __shared__ __align__(16) float h0ring[2][2][64];   // [slot][step] duplicated {h,h}
    __shared__ __align__(16) u64   pring[2][2][64];    // [slot][step] {i,f}/{g,o}
    __shared__ __align__(16) float h1ring[2][2][64];

    const int tid  = threadIdx.x;
    const int wid  = tid >> 5, j = tid & 31;
    const int role = (wid + blockIdx.x) % 3;           // rotated role mapping
    const int b    = blockIdx.x;

    // zero initial hidden states (all ring slots)
    for (int i = tid; i < 2 * 2 * 64; i += 96) {
        ((float*)h0ring)[i] = 0.f;
        ((float*)h1ring)[i] = 0.f;
    }

    // per-role weight matrix -> 64 u64 regs of gate-pair columns
    const float* Wsrc = (role == 0) ? Whh0 : (role == 1) ? Wih1 : Whh1;
    u64 w_if[32], w_go[32];
#pragma unroll
    for (int k = 0; k < 32; k++) {
        w_if[k] = pack2(Wsrc[j * 32 + k],        Wsrc[(32 + j) * 32 + k]);
        w_go[k] = pack2(Wsrc[(64 + j) * 32 + k], Wsrc[(96 + j) * 32 + k]);
    }

    u64 wx_if = 0, wx_go = 0, bs_if = 0, bs_go = 0;
    if (role == 0) {
        wx_if = pack2(Wih0[j],      Wih0[32 + j]);
        wx_go = pack2(Wih0[64 + j], Wih0[96 + j]);
        bs_if = pack2(bih0[j] + bhh0[j],           bih0[32 + j] + bhh0[32 + j]);
        bs_go = pack2(bih0[64 + j] + bhh0[64 + j], bih0[96 + j] + bhh0[96 + j]);
    } else if (role == 1) {
        bs_if = pack2(bih1[j] + bhh1[j],           bih1[32 + j] + bhh1[32 + j]);
        bs_go = pack2(bih1[64 + j] + bhh1[64 + j], bih1[96 + j] + bhh1[96 + j]);
    }

    float c   = 0.f;                   // cell state (roles 0 and 2)
    float xtA = x[b];                  // x[0], x[1]  (IN == 1)
    float xtB = x[B_SZ + b];

    __syncthreads();                   // init visible

#pragma unroll 1
    for (int n = 0; n < NTICK; n++) {
        if (role == 0) {
            if (n < T_SEQ / 2) {
                const int t0 = 2 * n;
                const int tpA = (t0 + 2 < T_SEQ) ? (t0 + 2) : (T_SEQ - 1);
                const int tpB = (t0 + 3 < T_SEQ) ? (t0 + 3) : (T_SEQ - 1);
                float xnA = x[tpA * B_SZ + b];         // prefetch next tick's x
                float xnB = x[tpB * B_SZ + b];
                u64 aif, ago;
                // step A: h0[2n] from h0[2n-1] (prev tick slot, step 1)
                matvec(reinterpret_cast<const ulonglong2*>(h0ring[(n + 1) & 1][1]),
                       w_if, w_go,
                       fma2(pack2(xtA, xtA), wx_if, bs_if),
                       fma2(pack2(xtA, xtA), wx_go, bs_go), aif, ago);
                float hA = cellstep(aif, ago, c);
                reinterpret_cast<u64*>(h0ring[n & 1][0])[j] = pack2(hA, hA);
                __syncwarp();
                // step B: h0[2n+1] from fresh h0[2n]
                matvec(reinterpret_cast<const ulonglong2*>(h0ring[n & 1][0]),
                       w_if, w_go,
                       fma2(pack2(xtB, xtB), wx_if, bs_if),
                       fma2(pack2(xtB, xtB), wx_go, bs_go), aif, ago);
                float hB = cellstep(aif, ago, c);
                reinterpret_cast<u64*>(h0ring[n & 1][1])[j] = pack2(hB, hB);
                xtA = xnA; xtB = xnB;
            }
        } else if (role == 1) {
            if (n >= 1 && n <= T_SEQ / 2) {
                const int s = (n - 1) & 1;
                u64 aifA, agoA, aifB, agoB;   // two INDEPENDENT matvecs
                matvec(reinterpret_cast<const ulonglong2*>(h0ring[s][0]),
                       w_if, w_go, bs_if, bs_go, aifA, agoA);
                matvec(reinterpret_cast<const ulonglong2*>(h0ring[s][1]),
                       w_if, w_go, bs_if, bs_go, aifB, agoB);
                pring[s][0][j]      = aifA;
                pring[s][0][32 + j] = agoA;
                pring[s][1][j]      = aifB;
                pring[s][1][32 + j] = agoB;
            }
        } else {
            if (n >= 2) {
                const int t0 = 2 * (n - 2);
                const int s  = n & 1;                  // slot (n-2)&1 == n&1
                u64 aif, ago;
                // step A: h1[t0] from h1[t0-1] (prev tick slot, step 1)
                matvec(reinterpret_cast<const ulonglong2*>(h1ring[(n + 1) & 1][1]),
                       w_if, w_go, pring[s][0][j], pring[s][0][32 + j], aif, ago);
                float hA = cellstep(aif, ago, c);
                reinterpret_cast<u64*>(h1ring[s][0])[j] = pack2(hA, hA);
                g_h1[(size_t)t0 * (B_SZ * 32) + b * 32 + j] = hA;     // coalesced
                __syncwarp();
                // step B: h1[t0+1] from fresh h1[t0]
                matvec(reinterpret_cast<const ulonglong2*>(h1ring[s][0]),
                       w_if, w_go, pring[s][1][j], pring[s][1][32 + j], aif, ago);
                float hB = cellstep(aif, ago, c);
                reinterpret_cast<u64*>(h1ring[s][1])[j] = pack2(hB, hB);
                g_h1[(size_t)(t0 + 1) * (B_SZ * 32) + b * 32 + j] = hB;
            }
        }
        __syncthreads();               // one 3-warp barrier per 2 timesteps
    }
}

// =====================================================================
// Dense head: out[t,b] = sum_j h1[t,b,j]*Wd[j] + bd. Memory-bound (~30us).
// =====================================================================
__global__ void __launch_bounds__(256)
k_head(const float* __restrict__ Wd, const float* __restrict__ bd,
       float* __restrict__ out)
{
    const int gw = blockIdx.x * 8 + (threadIdx.x >> 5);
    const int j  = threadIdx.x & 31;
    const size_t r = (size_t)gw * 4 + (j >> 3);
    const int q  = j & 7;

    float4 h = reinterpret_cast<const float4*>(g_h1)[r * 8 + q];
    float4 w = reinterpret_cast<const float4*>(Wd)[q];
    float s = h.x * w.x + h.y * w.y + h.z * w.z + h.w * w.w;
    s += __shfl_xor_sync(0xffffffffu, s, 1);
    s += __shfl_xor_sync(0xffffffffu, s, 2);
    s += __shfl_xor_sync(0xffffffffu, s, 4);
    if (q == 0) out[r] = s + bd[0];
}

// =====================================================================
extern "C" void kernel_launch(void* const* d_in, const int* in_sizes, int n_in,
                              void* d_out, int out_size)
{
    const float* x    = (const float*)d_in[0];
    const float* Wih0 = (const float*)d_in[1];
    const float* Whh0 = (const float*)d_in[2];
    const float* bih0 = (const float*)d_in[3];
    const float* bhh0 = (const float*)d_in[4];
    const float* Wih1 = (const float*)d_in[5];
    const float* Whh1 = (const float*)d_in[6];
    const float* bih1 = (const float*)d_in[7];
    const float* bhh1 = (const float*)d_in[8];
    const float* Wd   = (const float*)d_in[9];
    const float* bd   = (const float*)d_in[10];

    k_fused<<<512, 96>>>(x, Wih0, Whh0, bih0, bhh0, Wih1, Whh1, bih1, bhh1);
    k_head<<<32768, 256>>>(Wd, bd, (float*)d_out);
}